// round 12
// baseline (speedup 1.0000x reference)
#include <cuda_runtime.h>

// Problem constants (match reference)
#define NUM_CH   5
#define CROP_LO  70      // D//2 - 16, D = 173
#define CROP_HI  101     // CROP_LO + 32 - 1
#define CROP_N   32
#define CUBES    5
#define LATO     11      // 2*CUBES+1
#define RES2     0.0625f // RES*RES

// ONE kernel, one node, 160 blocks x 256 threads = 1280 warps.
// Each WARP autonomously owns one x-plane (32x32 floats, 4KB) of one
// (batch, channel) volume. No shared memory, no __syncthreads anywhere:
//   - issue all atom loads (2 atoms/lane) + zero own plane (overlapped)
//   - __syncwarp + threadfence_block (order own zeros before own REDs)
//   - ballot matching atoms, shuffle-broadcast, splat <=4 cells/lane/atom.
__global__ void __launch_bounds__(256) fused_voxelize_kernel(
    const float* __restrict__ coords,        // [B, N, 3]
    const int*   __restrict__ atoms_channel, // [B, N]
    const float* __restrict__ radius,        // [B, N]
    float* __restrict__ out,                 // [B, NUM_CH, 32, 32, 32]
    int n_per_batch)
{
    const int tid   = threadIdx.x;
    const int warp  = tid >> 5;
    const int lane  = tid & 31;
    const int bc    = blockIdx.x;                // b * NUM_CH + ch (0..39)
    const int b     = bc / NUM_CH;
    const int ch    = bc - b * NUM_CH;
    const int plane = blockIdx.y * 8 + warp;     // 0..31 (crop x coordinate)
    const int xcell = CROP_LO + plane;           // absolute grid x of this plane

    // --- preload 2 atoms per lane (all 10 LDGs issue up-front, MLP~10) ---
    const int a0 = lane;
    const int a1 = lane + 32;
    const bool v0 = (a0 < n_per_batch);
    const bool v1 = (a1 < n_per_batch);
    const int base = b * n_per_batch;
    float cx0 = 0.f, cy0 = 0.f, cz0 = 0.f, r0 = 1.f;  int c0 = -1;
    float cx1 = 0.f, cy1 = 0.f, cz1 = 0.f, r1 = 1.f;  int c1 = -1;
    if (v0) {
        cx0 = coords[3 * (base + a0) + 0];
        cy0 = coords[3 * (base + a0) + 1];
        cz0 = coords[3 * (base + a0) + 2];
        r0  = radius[base + a0];
        c0  = atoms_channel[base + a0];
    }
    if (v1) {
        cx1 = coords[3 * (base + a1) + 0];
        cy1 = coords[3 * (base + a1) + 1];
        cz1 = coords[3 * (base + a1) + 2];
        r1  = radius[base + a1];
        c1  = atoms_channel[base + a1];
    }

    // --- zero this warp's exclusive 4KB plane (overlaps the load latency) ---
    float* pl = out + (size_t)bc * (CROP_N * CROP_N * CROP_N)
                    + plane * (CROP_N * CROP_N);
    float4* dst = (float4*)pl;
    #pragma unroll
    for (int i = 0; i < (CROP_N * CROP_N / 4) / 32; ++i)   // 8 STG.128 per lane
        dst[lane + i * 32] = make_float4(0.f, 0.f, 0.f, 0.f);

    __syncwarp();
    __threadfence_block();   // order our zeros before our REDs (CTA scope)

    // --- two ballot rounds over the (up to 64) atoms of this batch ---
    #pragma unroll
    for (int round = 0; round < 2; ++round) {
        // this lane's candidate for the round
        const float mcx = round ? cx1 : cx0;
        const float mcy = round ? cy1 : cy0;
        const float mcz = round ? cz1 : cz0;
        const float mr  = round ? r1  : r0;
        const int   mc  = round ? c1  : c0;

        // does this lane's atom hit (channel, this x-plane)?
        const float msx = (mcx + 20.0f) * 4.0f + 6.0f;   // /0.25 == *4 exactly
        const int   mbx = (int)floorf(msx) - CUBES;
        const int   mox = xcell - mbx;                    // x offset in [0,10]?
        const bool  hit = (mc == ch) && (mox >= 0) && (mox <= LATO - 1);

        unsigned m = __ballot_sync(0xffffffffu, hit);
        while (m) {
            const int src = __ffs(m) - 1;
            m &= m - 1;
            // broadcast the owner's raw scalars (4 shuffles), rederive locally
            const float sx = __shfl_sync(0xffffffffu, msx, src);
            const float cy = __shfl_sync(0xffffffffu, mcy, src);
            const float cz = __shfl_sync(0xffffffffu, mcz, src);
            const float r  = __shfl_sync(0xffffffffu, mr,  src);

            const float sy = (cy + 20.0f) * 4.0f + 6.0f;
            const float sz = (cz + 20.0f) * 4.0f + 6.0f;
            const int bx = (int)floorf(sx) - CUBES;
            const int by = (int)floorf(sy) - CUBES;
            const int bz = (int)floorf(sz) - CUBES;

            const int y0 = max(0, CROP_LO - by), y1c = min(LATO - 1, CROP_HI - by);
            const int z0 = max(0, CROP_LO - bz), z1c = min(LATO - 1, CROP_HI - bz);
            const int ny = y1c - y0 + 1, nz = z1c - z0 + 1;
            if (ny <= 0 || nz <= 0) continue;

            const float coef = 0.5f * RES2 / (r * r);
            const float dx = sx - (float)xcell - 0.5f;    // fixed for this plane
            const float fy = sy - (float)(by + y0) - 0.5f;
            const float fz = sz - (float)(bz + z0) - 0.5f;
            const float e_x = -coef * dx * dx;            // fold x-term in

            const int   nyz = ny * nz;                    // <= 121
            const float rnz = 1.0f / (float)nz;
            float* p = pl + (by + y0 - CROP_LO) * CROP_N + (bz + z0 - CROP_LO);

            for (int k = lane; k < nyz; k += 32) {        // <= 4 iterations
                // exact small-int division via fp32 (k < 121, nz <= 11)
                int oy = (int)(((float)k + 0.5f) * rnz);
                int oz = k - oy * nz;
                float dy = fy - (float)oy;
                float dz = fz - (float)oz;
                float e  = fmaf(-coef, fmaf(dy, dy, dz * dz), e_x);
                atomicAdd(&p[oy * CROP_N + oz], __expf(e));
            }
        }
    }
}

extern "C" void kernel_launch(void* const* d_in, const int* in_sizes, int n_in,
                              void* d_out, int out_size) {
    const float* coords        = (const float*)d_in[0]; // [B,N,3]
    const int*   atoms_channel = (const int*)d_in[1];   // [B,N]
    const float* radius        = (const float*)d_in[2]; // [B,N]
    float* out = (float*)d_out;

    int n_atoms = in_sizes[1];                               // B*N = 512
    int B = out_size / (NUM_CH * CROP_N * CROP_N * CROP_N);  // 8
    int n_per_batch = n_atoms / B;                           // 64 (<=64 assumed)

    dim3 grid(B * NUM_CH, 4);   // 40 x 4 blocks, 8 warps each -> 1280 planes
    fused_voxelize_kernel<<<grid, 256>>>(coords, atoms_channel, radius, out,
                                         n_per_batch);
}

// round 13
// speedup vs baseline: 1.9373x; 1.9373x over previous
#include <cuda_runtime.h>

// Problem constants (match reference)
#define NUM_CH   5
#define CROP_LO  70      // D//2 - 16, D = 173
#define CROP_HI  101     // CROP_LO + 32 - 1
#define CROP_N   32
#define CUBES    5
#define LATO     11      // 2*CUBES+1
#define RES2     0.0625f // RES*RES

#define GROUP    128                 // threads per atom
#define APB      4                   // atoms per block
#define NTHREADS (GROUP * APB)       // 512

// Splat kernel: no smem, no barriers, no shuffles. Each 128-thread group owns
// one atom; every thread in the group loads the atom's 5 scalars itself
// (warp-uniform LDG -> L1 broadcast), derives identically, and splats its
// <=11 cells with predicated REDs. Zero-init is a preceding graph memset node.
__global__ void __launch_bounds__(NTHREADS) splat_kernel(
    const float* __restrict__ coords,        // [B, N, 3]
    const int*   __restrict__ atoms_channel, // [B, N]
    const float* __restrict__ radius,        // [B, N]
    float* __restrict__ out,                 // [B, NUM_CH, 32, 32, 32]
    int n_per_batch, int n_atoms)
{
    const int tid   = threadIdx.x;
    const int group = tid / GROUP;                 // 0..3
    const int gtid  = tid - group * GROUP;         // 0..127
    const int atom  = blockIdx.x * APB + group;
    if (atom >= n_atoms) return;
    const int b = atom / n_per_batch;

    // --- uniform scalar loads (all 5 issue independently, L1 broadcast) ---
    const float cx = coords[3 * atom + 0];
    const float cy = coords[3 * atom + 1];
    const float cz = coords[3 * atom + 2];
    const float r  = radius[atom];
    const int   ch = atoms_channel[atom];

    // scaled = (c + BOX)/RES + (CUBES+1); /0.25 == *4 exactly
    const float sx = (cx + 20.0f) * 4.0f + 6.0f;
    const float sy = (cy + 20.0f) * 4.0f + 6.0f;
    const float sz = (cz + 20.0f) * 4.0f + 6.0f;
    const int bx = (int)floorf(sx) - CUBES;
    const int by = (int)floorf(sy) - CUBES;
    const int bz = (int)floorf(sz) - CUBES;

    // clip splat box against crop window [CROP_LO, CROP_HI]
    const int x0 = max(0, CROP_LO - bx), x1 = min(LATO - 1, CROP_HI - bx);
    const int y0 = max(0, CROP_LO - by), y1 = min(LATO - 1, CROP_HI - by);
    const int z0 = max(0, CROP_LO - bz), z1 = min(LATO - 1, CROP_HI - bz);
    const int nx = x1 - x0 + 1, ny = y1 - y0 + 1, nz = z1 - z0 + 1;
    if (nx <= 0 || ny <= 0 || nz <= 0) return;     // splat misses the crop

    const float coef = 0.5f * RES2 / (r * r);
    const float fx = sx - (float)(bx + x0) - 0.5f;
    const float fy = sy - (float)(by + y0) - 0.5f;
    const float fz = sz - (float)(bz + z0) - 0.5f;

    const int nyz  = ny * nz;
    const int ntot = nx * nyz;                     // <= 1331
    const float rnyz = 1.0f / (float)nyz;
    const float rnz  = 1.0f / (float)nz;

    float* __restrict__ p = out
        + (size_t)(b * NUM_CH + ch) * (CROP_N * CROP_N * CROP_N)
        + ((bx + x0 - CROP_LO) * CROP_N + (by + y0 - CROP_LO)) * CROP_N
        + (bz + z0 - CROP_LO);

    for (int k = gtid; k < ntot; k += GROUP) {     // <= 11 iterations
        // exact small-int division via fp32 (k < 1331, divisors <= 121)
        int ox  = (int)(((float)k + 0.5f) * rnyz);
        int rem = k - ox * nyz;
        int oy  = (int)(((float)rem + 0.5f) * rnz);
        int oz  = rem - oy * nz;
        float dx = fx - (float)ox;
        float dy = fy - (float)oy;
        float dz = fz - (float)oz;
        float d2 = fmaf(dx, dx, fmaf(dy, dy, dz * dz));
        float v  = __expf(-coef * d2);
        atomicAdd(&p[(ox * CROP_N + oy) * CROP_N + oz], v);
    }
}

extern "C" void kernel_launch(void* const* d_in, const int* in_sizes, int n_in,
                              void* d_out, int out_size) {
    const float* coords        = (const float*)d_in[0]; // [B,N,3]
    const int*   atoms_channel = (const int*)d_in[1];   // [B,N]
    const float* radius        = (const float*)d_in[2]; // [B,N]
    float* out = (float*)d_out;

    int n_atoms = in_sizes[1];                               // B*N = 512
    int B = out_size / (NUM_CH * CROP_N * CROP_N * CROP_N);  // 8
    int n_per_batch = n_atoms / B;                           // 64

    // Zero output via graph memset node (proven ~free, provides ordering)
    cudaMemsetAsync(out, 0, (size_t)out_size * sizeof(float));

    // 4 atoms per block -> 128 blocks (measured grid sweet spot)
    int blocks = (n_atoms + APB - 1) / APB;
    splat_kernel<<<blocks, NTHREADS>>>(coords, atoms_channel, radius, out,
                                       n_per_batch, n_atoms);
}